// round 5
// baseline (speedup 1.0000x reference)
#include <cuda_runtime.h>
#include <stdint.h>

// Embedding gather: out[j*64+k] = pages[idx[j]*64+k]
// pages [8,125000,64] contiguous; (i/P)*P + i%P == i -> flat gather at idx[j]*64.
// indices int32 (JAX default x64-disabled).
//
// ILP=8, exact-grid (no bounds predicates), 32-bit offset arithmetic.
// Phase-structured: 8 idx loads -> 8 independent 16B table gathers -> 8
// streaming stores. Per-warp outstanding LDGs ~16+ to cover L2-hit latency
// (~250 cyc), which R3's profile showed is the binding constraint.

#define N_WORDS 1000000
#define ILP 8
#define THREADS 256

__global__ void __launch_bounds__(THREADS) emb_gather_fast(
        const int* __restrict__ idx,
        const float4* __restrict__ pages4,
        float4* __restrict__ out4) {
    const unsigned S = gridDim.x * THREADS;          // total threads
    const unsigned t0 = blockIdx.x * THREADS + threadIdx.x;

    // Phase 1: index loads (independent) + offset math (32-bit: i*16+c < 2^24)
    unsigned off[ILP];
    #pragma unroll
    for (int u = 0; u < ILP; u++) {
        unsigned t = t0 + u * S;
        unsigned j = t >> 4;
        unsigned c = t & 15u;
        int iv = __ldg(&idx[j]);
        iv = max(0, min(iv, N_WORDS - 1));           // defensive, 2 ALU ops
        off[u] = (unsigned)iv * 16u + c;
    }

    // Phase 2: 8 independent table gathers (MLP=8/thread)
    float4 d[ILP];
    #pragma unroll
    for (int u = 0; u < ILP; u++) d[u] = __ldg(&pages4[off[u]]);

    // Phase 3: streaming stores (evict-first; protect table's L2 residency)
    #pragma unroll
    for (int u = 0; u < ILP; u++) __stcs(&out4[t0 + u * S], d[u]);
}

// Fallback with bounds checks for shapes not divisible by THREADS*ILP.
__global__ void __launch_bounds__(THREADS) emb_gather_safe(
        const int* __restrict__ idx,
        const float4* __restrict__ pages4,
        float4* __restrict__ out4,
        long long n_vec) {
    long long t = (long long)blockIdx.x * THREADS + threadIdx.x;
    if (t >= n_vec) return;
    long long j = t >> 4;
    int c = (int)(t & 15);
    int iv = __ldg(&idx[j]);
    iv = max(0, min(iv, N_WORDS - 1));
    __stcs(&out4[t], __ldg(&pages4[(long long)iv * 16 + c]));
}

extern "C" void kernel_launch(void* const* d_in, const int* in_sizes, int n_in,
                              void* d_out, int out_size) {
    const int*   idx   = (const int*)d_in[0];    // [16,8192] int32
    const float* pages = (const float*)d_in[1];  // [8,125000,64] fp32

    long long n_lookups = in_sizes[0];           // 131072
    long long n_vec = n_lookups * 16;            // 2,097,152 float4s

    const long long chunk = (long long)THREADS * ILP;   // 2048 vec/block
    if (n_vec % chunk == 0) {
        int blocks = (int)(n_vec / chunk);               // 1024
        emb_gather_fast<<<blocks, THREADS>>>(
            idx, (const float4*)pages, (float4*)d_out);
    } else {
        int blocks = (int)((n_vec + THREADS - 1) / THREADS);
        emb_gather_safe<<<blocks, THREADS>>>(
            idx, (const float4*)pages, (float4*)d_out, n_vec);
    }
}